// round 7
// baseline (speedup 1.0000x reference)
#include <cuda_runtime.h>
#include <math.h>

#define T_DIM 1024
#define EPS 1e-7f
#define MARGIN 0.1f
#define MONO_W 0.1f
#define BETA 0.1f

#define BDIM 256            // 256 threads * float4 = 1024 cols = one row
#define ROWS 8              // rows per group
#define NBLK 740            // 5 blocks/SM * 148 SMs (persistent)
#define FDIM 1024           // finalize block size

// Deterministic per-block partials (bce, mono, cnt, pad): each block fully
// overwrites its own slot at the END of the persistent kernel -> L2-hot for
// the finalize kernel; no init pass, no atomics.
__device__ float4 g_partials[1024];

__device__ __forceinline__ float warp_red(float v) {
#pragma unroll
    for (int o = 16; o > 0; o >>= 1) v += __shfl_down_sync(0xFFFFFFFFu, v, o);
    return v;
}
__device__ __forceinline__ double warp_red_d(double v) {
#pragma unroll
    for (int o = 16; o > 0; o >>= 1) v += __shfl_down_sync(0xFFFFFFFFu, v, o);
    return v;
}

__global__ __launch_bounds__(BDIM, 5) void cdf_loss_main(
    const float* __restrict__ F,
    const long long* __restrict__ duration,
    const long long* __restrict__ event_in,
    int ngroups)
{
    const int tid  = threadIdx.x;
    const int lane = tid & 31;
    const int wid  = tid >> 5;
    const int c0   = tid * 4;

    // double-buffered boundary values: one barrier per group, next group's
    // loads/stores overlap previous group's compute
    __shared__ float s_first[2][ROWS][BDIM];

    float bce = 0.0f;
    float mono = 0.0f;
    int cnt = 0;
    int buf = 0;

    for (int g = blockIdx.x; g < ngroups; g += NBLK) {
        const int row0 = g * ROWS;

        // per-row metadata packed: d | (e << 16)
        int meta[ROWS];
#pragma unroll
        for (int r = 0; r < ROWS; ++r) {
            const int dd = (int)duration[row0 + r];
            const int ee = (int)event_in[row0 + r];
            meta[r] = dd | (ee << 16);
        }

        // front-batched independent bulk loads (MLP = ROWS)
        float4 v[ROWS];
#pragma unroll
        for (int r = 0; r < ROWS; ++r) {
            const float4* rowp = reinterpret_cast<const float4*>(F + (size_t)(row0 + r) * T_DIM);
            v[r] = rowp[tid];
        }

#pragma unroll
        for (int r = 0; r < ROWS; ++r)
            s_first[buf][r][tid] = v[r].x;
        __syncthreads();   // single barrier per group (double buffering)

#pragma unroll
        for (int r = 0; r < ROWS; ++r) {
            const float4 w = v[r];

            // ---- monotonic term (verified mechanism) ----
            mono += fmaxf(w.x - w.y + MARGIN, 0.0f);
            mono += fmaxf(w.y - w.z + MARGIN, 0.0f);
            mono += fmaxf(w.z - w.w + MARGIN, 0.0f);
            if (tid < BDIM - 1)
                mono += fmaxf(w.w - s_first[buf][r][tid + 1] + MARGIN, 0.0f);

            // ---- BCE term (verified math) ----
            const float vals[4] = {w.x, w.y, w.z, w.w};
            const int dd = meta[r] & 0xFFFF;
            const int ee = meta[r] >> 16;
#pragma unroll
            for (int k = 0; k < 4; ++k) {
                const int c = c0 + k;
                const bool m = ee ? true : (c <= dd);
                if (m) {
                    cnt++;
                    const float p = fminf(fmaxf(vals[k], EPS), 1.0f - EPS);
                    const bool tgt = ee && (c >= dd);
                    bce += -__logf(tgt ? p : (1.0f - p));
                }
            }
        }
        buf ^= 1;
    }

    // ---- block reduction ----
    bce  = warp_red(bce);
    mono = warp_red(mono);
    float cf = warp_red((float)cnt);

    __shared__ float sh_b[BDIM / 32];
    __shared__ float sh_m[BDIM / 32];
    __shared__ float sh_c[BDIM / 32];
    if (lane == 0) { sh_b[wid] = bce; sh_m[wid] = mono; sh_c[wid] = cf; }
    __syncthreads();
    if (wid == 0) {
        bce  = (lane < BDIM / 32) ? sh_b[lane] : 0.0f;
        mono = (lane < BDIM / 32) ? sh_m[lane] : 0.0f;
        cf   = (lane < BDIM / 32) ? sh_c[lane] : 0.0f;
        bce = warp_red(bce);
        mono = warp_red(mono);
        cf  = warp_red(cf);
        if (lane == 0)
            g_partials[blockIdx.x] = make_float4(bce, mono, cf, 0.0f);
    }
}

__global__ __launch_bounds__(FDIM) void cdf_loss_finalize(
    const float* __restrict__ biases,
    float* __restrict__ out, int B, int nblk)
{
    const int tid = threadIdx.x;
    const int lane = tid & 31, wid = tid >> 5;

    // nblk = 740 <= FDIM: each thread loads at most one (L2-hot) partial
    double sb = 0.0, sm = 0.0, sc = 0.0;
    if (tid < nblk) {
        const float4 p = g_partials[tid];
        sb = (double)p.x; sm = (double)p.y; sc = (double)p.z;
    }

    float s = (tid < T_DIM) ? biases[tid] : 0.0f;
    s = s * s;

    sb = warp_red_d(sb);
    sm = warp_red_d(sm);
    sc = warp_red_d(sc);
    s  = warp_red(s);

    __shared__ double shb[FDIM / 32], shm[FDIM / 32], shc[FDIM / 32];
    __shared__ float  shs[FDIM / 32];
    if (lane == 0) { shb[wid] = sb; shm[wid] = sm; shc[wid] = sc; shs[wid] = s; }
    __syncthreads();
    if (wid == 0) {
        sb = (lane < FDIM / 32) ? shb[lane] : 0.0;
        sm = (lane < FDIM / 32) ? shm[lane] : 0.0;
        sc = (lane < FDIM / 32) ? shc[lane] : 0.0;
        s  = (lane < FDIM / 32) ? shs[lane] : 0.0f;
        sb = warp_red_d(sb);
        sm = warp_red_d(sm);
        sc = warp_red_d(sc);
        s  = warp_red(s);
        if (lane == 0) {
            const double bceL  = sb / sc;
            const double monoL = sm / ((double)B * (double)(T_DIM - 1));
            const double bias2 = (double)s / (double)T_DIM;
            out[0] = (float)(bceL + (double)MONO_W * monoL + (double)BETA * bias2);
        }
    }
}

extern "C" void kernel_launch(void* const* d_in, const int* in_sizes, int n_in,
                              void* d_out, int out_size) {
    const float*     F      = (const float*)d_in[0];      // [B, T] fp32
    const float*     biases = (const float*)d_in[1];      // [T] fp32
    const long long* dur    = (const long long*)d_in[2];  // [B] int64
    const long long* ev     = (const long long*)d_in[3];  // [B] int64
    float* out = (float*)d_out;

    const int B = in_sizes[2];
    const int ngroups = B / ROWS;

    cdf_loss_main<<<NBLK, BDIM>>>(F, dur, ev, ngroups);
    cdf_loss_finalize<<<1, FDIM>>>(biases, out, B, NBLK);
}